// round 2
// baseline (speedup 1.0000x reference)
#include <cuda_runtime.h>
#include <cstdint>
#include <cstddef>

// Problem constants
#define BDIM 8
#define DDIM 256
#define TDIM 8192
#define NQ 8
#define BINS 1024
#define TT 64                        // tokens per CTA
#define NB 64                        // bins per chunk
#define NCHUNK 16                    // chunks per stage
#define NG (NQ * NCHUNK)             // 128 total chunks
#define RS 260                       // padded row stride (floats): 1040B -> lane-rotated bank groups
#define NTILE ((BDIM * TDIM) / TT)   // 1024 CTAs
#define QELEMS (BDIM * DDIM * TDIM)  // 16777216
#define CELEMS (NQ * BDIM * TDIM)    // 524288

// SMEM layout (float offsets)
#define OFF_R 0
#define OFF_C0 (TT * RS)
#define OFF_C1 (2 * TT * RS)
#define OFF_CSQ (3 * TT * RS)        // 64 floats  (49920)
#define OFF_IDX (OFF_CSQ + 64)       // 64 ints
#define OFF_RD (OFF_IDX + 64)        // 128 floats
#define OFF_RI (OFF_RD + 128)        // 128 ints
#define OFF_WD (OFF_RI + 128)        // 8 doubles (byte off 201216, 8B aligned)
#define OFF_FLAG (OFF_WD + 16)       // 1 int
#define SMEM_FLOATS (OFF_FLAG + 8)
#define SMEM_BYTES (SMEM_FLOATS * 4) // ~201.4 KB

__device__ double   g_losspart[NTILE];
__device__ unsigned g_ctr;

// ---------------------------------------------------------------------------
// Async prefetch of one 64-bin codebook chunk into SMEM (row-padded to RS).
// ---------------------------------------------------------------------------
__device__ __forceinline__ void prefetch_chunk(const float* __restrict__ cbs,
                                               int g, float* __restrict__ sCbuf,
                                               int tid) {
    int s = g >> 4, c = g & 15;
    const float* src = cbs + (size_t)(s * BINS + c * NB) * DDIM;
    unsigned dstbase = (unsigned)__cvta_generic_to_shared(sCbuf);
#pragma unroll
    for (int it = 0; it < 16; ++it) {
        int f   = tid + it * 256;   // float4 index, 0..4095
        int row = f >> 6;           // bin row 0..63
        int c4  = f & 63;           // float4 within row
        unsigned     dst = dstbase + (unsigned)((row * RS + c4 * 4) * 4);
        const float* gp  = src + row * DDIM + c4 * 4;
        asm volatile("cp.async.cg.shared.global [%0], [%1], 16;\n" ::"r"(dst), "l"(gp));
    }
    asm volatile("cp.async.commit_group;\n");
}

// pure computation: non-volatile so ptxas can schedule/pipeline freely
#define FMA2(d, a, b) \
    asm("fma.rn.f32x2 %0, %1, %2, %0;" : "+l"(d) : "l"(a), "l"(b))

// ---------------------------------------------------------------------------
// Fully fused RVQ kernel. One CTA = 64 tokens.
// Warp footprint: 16 tokens x 32 bins (thread = 2 tok x 8 bins) -> smem
// traffic 768B per warp k4-iter (37% of crossbar vs 75% before).
// ---------------------------------------------------------------------------
__global__ __launch_bounds__(256, 1) void rvq_main(const float* __restrict__ x,
                                                   const float* __restrict__ cbs,
                                                   const int* __restrict__ srp,
                                                   float* __restrict__ out) {
    extern __shared__ float sm[];
    float*  sR   = sm + OFF_R;
    float*  sCsq = sm + OFF_CSQ;
    int*    sIdx = (int*)(sm + OFF_IDX);
    float*  sRd  = sm + OFF_RD;
    int*    sRi  = (int*)(sm + OFF_RI);
    double* sWD  = (double*)(sm + OFF_WD);
    int*    sFlg = (int*)(sm + OFF_FLAG);

    const int tid = threadIdx.x;
    const int w   = tid >> 5;
    const int l   = tid & 31;
    const int wty = w >> 1;     // token block (16 tokens)
    const int wtx = w & 1;      // bin half (32 bins)
    const int lty = l >> 2;     // 0..7
    const int ltx = l & 3;      // 0..3
    const int b   = blockIdx.x >> 7;
    const int t0  = (blockIdx.x & 127) * TT;

    float* out_q = out;
    float* out_c = out + QELEMS;

    // ---- prologue: load + transpose x tile into sR[t][k] ----
#pragma unroll
    for (int it = 0; it < 16; ++it) {
        int f  = tid + it * 256;
        int k  = f >> 4;
        int t4 = f & 15;
        float4 v = *(const float4*)(x + (size_t)(b * DDIM + k) * TDIM + t0 + t4 * 4);
        int tl = t4 * 4;
        sR[(tl + 0) * RS + k] = v.x;
        sR[(tl + 1) * RS + k] = v.y;
        sR[(tl + 2) * RS + k] = v.z;
        sR[(tl + 3) * RS + k] = v.w;
    }
    prefetch_chunk(cbs, 0, sm + OFF_C0, tid);

    double lossLocal = 0.0;
    const int   tb = wty * 16 + lty;        // thread tokens: tb, tb+8
    const float* Rb = sR + tb * RS;

    for (int s = 0; s < NQ; ++s) {
        float bd[2] = {3.4e38f, 3.4e38f};
        int   bi[2] = {0, 0};

        for (int c = 0; c < NCHUNK; ++c) {
            int g = s * NCHUNK + c;
            float* sC = sm + ((g & 1) ? OFF_C1 : OFF_C0);

            asm volatile("cp.async.wait_group 0;\n");
            __syncthreads();   // chunk g visible everywhere; everyone done with g-1

            // early prefetch of g+1 into the buffer chunk g-1 used (safe: synced)
            if (g + 1 < NG)
                prefetch_chunk(cbs, g + 1, sm + ((g & 1) ? OFF_C0 : OFF_C1), tid);

            // ---- per-chunk ||c||^2 from resident SMEM tile ----
            {
                int bin = tid >> 2, q = tid & 3;
                const float* p = sC + bin * RS + q * 64;
                float ss = 0.f;
#pragma unroll
                for (int i = 0; i < 16; ++i) {
                    float4 v = *(const float4*)(p + i * 4);
                    ss = fmaf(v.x, v.x, fmaf(v.y, v.y, fmaf(v.z, v.z, fmaf(v.w, v.w, ss))));
                }
                ss += __shfl_xor_sync(0xffffffffu, ss, 1);
                ss += __shfl_xor_sync(0xffffffffu, ss, 2);
                if (q == 0) sCsq[bin] = ss;
            }
            __syncthreads();   // sCsq visible (warps already aligned: cheap)

            const float* Cb = sC + (wtx * 32 + ltx) * RS;

            ulonglong2 acc[2][8];
#pragma unroll
            for (int i = 0; i < 2; ++i)
#pragma unroll
                for (int j = 0; j < 8; ++j) { acc[i][j].x = 0ull; acc[i][j].y = 0ull; }

#pragma unroll 4
            for (int k4 = 0; k4 < DDIM; k4 += 4) {
                ulonglong2 r0 = *(const ulonglong2*)(Rb + k4);
                ulonglong2 r1 = *(const ulonglong2*)(Rb + 8 * RS + k4);
                ulonglong2 cc[8];
#pragma unroll
                for (int j = 0; j < 8; ++j)
                    cc[j] = *(const ulonglong2*)(Cb + j * 4 * RS + k4);
#pragma unroll
                for (int j = 0; j < 8; ++j) {   // j-inner: r0 in same slot -> .reuse
                    FMA2(acc[0][j].x, r0.x, cc[j].x);
                    FMA2(acc[0][j].y, r0.y, cc[j].y);
                }
#pragma unroll
                for (int j = 0; j < 8; ++j) {
                    FMA2(acc[1][j].x, r1.x, cc[j].x);
                    FMA2(acc[1][j].y, r1.y, cc[j].y);
                }
            }

            // ---- distances + running argmin (j ascending = bins ascending) ----
#pragma unroll
            for (int i = 0; i < 2; ++i)
#pragma unroll
                for (int j = 0; j < 8; ++j) {
                    float ax, ay, bx, by;
                    asm("mov.b64 {%0,%1}, %2;" : "=f"(ax), "=f"(ay) : "l"(acc[i][j].x));
                    asm("mov.b64 {%0,%1}, %2;" : "=f"(bx), "=f"(by) : "l"(acc[i][j].y));
                    float dot  = (ax + ay) + (bx + by);
                    int   binl = wtx * 32 + j * 4 + ltx;
                    float dist = fmaf(-2.f, dot, sCsq[binl]);
                    int   bing = c * NB + binl;
                    if (dist < bd[i]) { bd[i] = dist; bi[i] = bing; }
                }
        }

        // ---- lexicographic reduce over the 4 ltx lanes ----
#pragma unroll
        for (int o = 1; o < 4; o <<= 1) {
#pragma unroll
            for (int i = 0; i < 2; ++i) {
                float od = __shfl_xor_sync(0xffffffffu, bd[i], o);
                int   oi = __shfl_xor_sync(0xffffffffu, bi[i], o);
                if (od < bd[i] || (od == bd[i] && oi < bi[i])) { bd[i] = od; bi[i] = oi; }
            }
        }
        if (ltx == 0) {
            sRd[wtx * 64 + tb]     = bd[0];  sRi[wtx * 64 + tb]     = bi[0];
            sRd[wtx * 64 + tb + 8] = bd[1];  sRi[wtx * 64 + tb + 8] = bi[1];
        }
        __syncthreads();

        if (tid < TT) {
            float d0 = sRd[tid], d1 = sRd[64 + tid];
            int   i0 = sRi[tid], i1 = sRi[64 + tid];
            int idx = (d1 < d0 || (d1 == d0 && i1 < i0)) ? i1 : i0;
            sIdx[tid] = idx;
            out_c[(size_t)(s * BDIM + b) * TDIM + t0 + tid] = (float)idx;
        }
        __syncthreads();

        // ---- residual update + commitment loss ----
        {
            int t   = tid >> 2;
            int ko  = (tid & 3) * 64;
            int idx = sIdx[t];
            const float4* cv = (const float4*)(cbs + (size_t)(s * BINS + idx) * DDIM + ko);
            float* rp = sR + t * RS + ko;
            float  lsum = 0.f;
#pragma unroll
            for (int q = 0; q < 16; ++q) {
                float4 v  = cv[q];
                float a0 = rp[q * 4 + 0] - v.x;
                float a1 = rp[q * 4 + 1] - v.y;
                float a2 = rp[q * 4 + 2] - v.z;
                float a3 = rp[q * 4 + 3] - v.w;
                rp[q * 4 + 0] = a0; rp[q * 4 + 1] = a1;
                rp[q * 4 + 2] = a2; rp[q * 4 + 3] = a3;
                lsum += a0 * a0 + a1 * a1 + a2 * a2 + a3 * a3;
            }
            lossLocal += (double)lsum;
        }
        // next chunk-loop top sync orders sR writes before GEMM reads
    }
    __syncthreads();

    // ---- epilogue: quantized = x - final residual ----
#pragma unroll
    for (int it = 0; it < 16; ++it) {
        int f  = tid + it * 256;
        int k  = f >> 4;
        int t4 = f & 15;
        const float4 v = *(const float4*)(x + (size_t)(b * DDIM + k) * TDIM + t0 + t4 * 4);
        int tl = t4 * 4;
        float4 o;
        o.x = v.x - sR[(tl + 0) * RS + k];
        o.y = v.y - sR[(tl + 1) * RS + k];
        o.z = v.z - sR[(tl + 2) * RS + k];
        o.w = v.w - sR[(tl + 3) * RS + k];
        *(float4*)(out_q + (size_t)(b * DDIM + k) * TDIM + t0 + t4 * 4) = o;
    }

    // ---- per-CTA loss partial (deterministic) ----
    int lane = tid & 31;
#pragma unroll
    for (int o = 16; o; o >>= 1) lossLocal += __shfl_down_sync(0xffffffffu, lossLocal, o);
    if (lane == 0) sWD[w] = lossLocal;
    __syncthreads();
    if (tid == 0) {
        double t = 0.0;
        for (int i = 0; i < 8; ++i) t += sWD[i];
        g_losspart[blockIdx.x] = t;
        __threadfence();
        unsigned old = atomicAdd(&g_ctr, 1u);
        *sFlg = (old == NTILE - 1) ? 1 : 0;
    }
    __syncthreads();

    // ---- last CTA finalizes scalars (fixed-order, deterministic) ----
    if (*sFlg && tid < 32) {
        __threadfence();
        double ssum = 0.0;
        for (int i = lane; i < NTILE; i += 32) ssum += __ldcg(&g_losspart[i]);
#pragma unroll
        for (int o = 16; o; o >>= 1) ssum += __shfl_down_sync(0xffffffffu, ssum, o);
        if (lane == 0) {
            int   iv = *srp;
            float fv = __int_as_float(iv);
            double sr = (iv > 0 && iv < 100000000) ? (double)iv : (double)fv;
            out[QELEMS + CELEMS]     = (float)((double)NQ * 10.0 * sr / 1000.0);
            out[QELEMS + CELEMS + 1] = (float)(ssum / (4.0 * (double)NQ * (double)QELEMS));
            atomicExch(&g_ctr, 0u);   // reset for next replay
        }
    }
}

// ---------------------------------------------------------------------------
extern "C" void kernel_launch(void* const* d_in, const int* in_sizes, int n_in,
                              void* d_out, int out_size) {
    const float* x   = nullptr;
    const float* cbs = nullptr;
    const int*   srp = nullptr;
    for (int i = 0; i < n_in; ++i) {
        if (in_sizes[i] == QELEMS)                x   = (const float*)d_in[i];
        else if (in_sizes[i] == NQ * BINS * DDIM) cbs = (const float*)d_in[i];
        else                                      srp = (const int*)d_in[i];
    }
    float* out = (float*)d_out;

    cudaFuncSetAttribute(rvq_main, cudaFuncAttributeMaxDynamicSharedMemorySize, SMEM_BYTES);
    rvq_main<<<NTILE, 256, SMEM_BYTES>>>(x, cbs, srp, out);
}

// round 6
// speedup vs baseline: 1.0689x; 1.0689x over previous
#include <cuda_runtime.h>
#include <cstdint>
#include <cstddef>

// Problem constants
#define BDIM 8
#define DDIM 256
#define TDIM 8192
#define NQ 8
#define BINS 1024
#define TT 64                        // tokens per CTA
#define NB 64                        // bins per chunk
#define NCHUNK 16                    // chunks per stage
#define NG (NQ * NCHUNK)             // 128 total chunks
#define RS 260                       // padded row stride (floats)
#define NTILE ((BDIM * TDIM) / TT)   // 1024 CTAs
#define QELEMS (BDIM * DDIM * TDIM)  // 16777216
#define CELEMS (NQ * BDIM * TDIM)    // 524288

// SMEM layout (float offsets)
#define OFF_R 0
#define OFF_C0 (TT * RS)
#define OFF_C1 (2 * TT * RS)
#define OFF_IDX (3 * TT * RS)        // 64 ints
#define OFF_RD (OFF_IDX + 64)        // 128 floats
#define OFF_RI (OFF_RD + 128)        // 128 ints
#define OFF_WD (OFF_RI + 128)        // 8 doubles (8B aligned)
#define OFF_FLAG (OFF_WD + 16)       // 1 int
#define SMEM_FLOATS (OFF_FLAG + 8)
#define SMEM_BYTES (SMEM_FLOATS * 4) // ~200.4 KB

__device__ float    g_cbsq[NQ * BINS];
__device__ double   g_losspart[NTILE];
__device__ unsigned g_ctr;

// ---------------------------------------------------------------------------
// Precompute ||c||^2 per codebook row. One warp per bin.
// ---------------------------------------------------------------------------
__global__ void cbsq_kernel(const float* __restrict__ cbs) {
    int gid  = blockIdx.x * blockDim.x + threadIdx.x;
    int w    = gid >> 5;
    int lane = gid & 31;
    const float* row = cbs + (size_t)w * DDIM;
    float s = 0.f;
#pragma unroll
    for (int k = 0; k < DDIM; k += 32) {
        float v = row[k + lane];
        s = fmaf(v, v, s);
    }
#pragma unroll
    for (int o = 16; o; o >>= 1) s += __shfl_xor_sync(0xffffffffu, s, o);
    if (lane == 0) g_cbsq[w] = s;
}

// ---------------------------------------------------------------------------
// Async prefetch of one 64-bin codebook chunk into SMEM (row-padded to RS).
// ---------------------------------------------------------------------------
__device__ __forceinline__ void prefetch_chunk(const float* __restrict__ cbs,
                                               int g, float* __restrict__ sCbuf,
                                               int tid) {
    int s = g >> 4, c = g & 15;
    const float* src = cbs + (size_t)(s * BINS + c * NB) * DDIM;
    unsigned dstbase = (unsigned)__cvta_generic_to_shared(sCbuf);
#pragma unroll
    for (int it = 0; it < 16; ++it) {
        int f   = tid + it * 256;
        int row = f >> 6;
        int c4  = f & 63;
        unsigned     dst = dstbase + (unsigned)((row * RS + c4 * 4) * 4);
        const float* gp  = src + row * DDIM + c4 * 4;
        asm volatile("cp.async.cg.shared.global [%0], [%1], 16;\n" ::"r"(dst), "l"(gp));
    }
    asm volatile("cp.async.commit_group;\n");
}

// non-volatile: pure computation, ptxas may schedule freely
#define FMA2(d, a, b) \
    asm("fma.rn.f32x2 %0, %1, %2, %0;" : "+l"(d) : "l"(a), "l"(b))

// ---------------------------------------------------------------------------
// Fused RVQ kernel. One CTA = 64 tokens, residual resident in SMEM.
// Warp footprint 16 tok x 32 bins (thread = 2 tok x 8 bins).
// Single f32x2 accumulator per (tok,bin): 32 acc regs total -> no spills.
// ---------------------------------------------------------------------------
__global__ __launch_bounds__(256, 2) void rvq_main(const float* __restrict__ x,
                                                   const float* __restrict__ cbs,
                                                   const int* __restrict__ srp,
                                                   float* __restrict__ out) {
    extern __shared__ float sm[];
    float*  sR   = sm + OFF_R;
    int*    sIdx = (int*)(sm + OFF_IDX);
    float*  sRd  = sm + OFF_RD;
    int*    sRi  = (int*)(sm + OFF_RI);
    double* sWD  = (double*)(sm + OFF_WD);
    int*    sFlg = (int*)(sm + OFF_FLAG);

    const int tid = threadIdx.x;
    const int w   = tid >> 5;
    const int l   = tid & 31;
    const int wty = w >> 1;     // token block (16 tokens)
    const int wtx = w & 1;      // bin half (32 bins)
    const int lty = l >> 2;     // 0..7
    const int ltx = l & 3;      // 0..3
    const int b   = blockIdx.x >> 7;
    const int t0  = (blockIdx.x & 127) * TT;

    float* out_q = out;
    float* out_c = out + QELEMS;

    // ---- prologue: load + transpose x tile into sR[t][k] ----
#pragma unroll
    for (int it = 0; it < 16; ++it) {
        int f  = tid + it * 256;
        int k  = f >> 4;
        int t4 = f & 15;
        float4 v = *(const float4*)(x + (size_t)(b * DDIM + k) * TDIM + t0 + t4 * 4);
        int tl = t4 * 4;
        sR[(tl + 0) * RS + k] = v.x;
        sR[(tl + 1) * RS + k] = v.y;
        sR[(tl + 2) * RS + k] = v.z;
        sR[(tl + 3) * RS + k] = v.w;
    }
    prefetch_chunk(cbs, 0, sm + OFF_C0, tid);

    double lossLocal = 0.0;
    const int    tb = wty * 16 + lty;       // thread tokens: tb, tb+8
    const float* Rb = sR + tb * RS;

    for (int s = 0; s < NQ; ++s) {
        float bd[2] = {3.4e38f, 3.4e38f};
        int   bi[2] = {0, 0};

        for (int c = 0; c < NCHUNK; ++c) {
            int g = s * NCHUNK + c;
            const float* sC = sm + ((g & 1) ? OFF_C1 : OFF_C0);

            asm volatile("cp.async.wait_group 0;\n");
            __syncthreads();   // chunk g visible; everyone done with g-1 buffer

            if (g + 1 < NG)
                prefetch_chunk(cbs, g + 1, sm + ((g & 1) ? OFF_C0 : OFF_C1), tid);

            const float* Cb = sC + (wtx * 32 + ltx) * RS;

            // single f32x2 accumulator per (tok,bin)
            unsigned long long acc[2][8];
#pragma unroll
            for (int i = 0; i < 2; ++i)
#pragma unroll
                for (int j = 0; j < 8; ++j) acc[i][j] = 0ull;

#pragma unroll 4
            for (int k4 = 0; k4 < DDIM; k4 += 4) {
                ulonglong2 r0 = *(const ulonglong2*)(Rb + k4);
                ulonglong2 r1 = *(const ulonglong2*)(Rb + 8 * RS + k4);
                ulonglong2 cc[8];
#pragma unroll
                for (int j = 0; j < 8; ++j)
                    cc[j] = *(const ulonglong2*)(Cb + j * 4 * RS + k4);
#pragma unroll
                for (int j = 0; j < 8; ++j) {
                    FMA2(acc[0][j], r0.x, cc[j].x);
                    FMA2(acc[0][j], r0.y, cc[j].y);
                }
#pragma unroll
                for (int j = 0; j < 8; ++j) {
                    FMA2(acc[1][j], r1.x, cc[j].x);
                    FMA2(acc[1][j], r1.y, cc[j].y);
                }
            }

            // ---- distances + running argmin (j ascending = bins ascending) ----
            const float* csq = &g_cbsq[s * BINS + c * NB];
#pragma unroll
            for (int i = 0; i < 2; ++i)
#pragma unroll
                for (int j = 0; j < 8; ++j) {
                    float ax, ay;
                    asm("mov.b64 {%0,%1}, %2;" : "=f"(ax), "=f"(ay) : "l"(acc[i][j]));
                    float dot  = ax + ay;
                    int   binl = wtx * 32 + j * 4 + ltx;
                    float dist = fmaf(-2.f, dot, __ldg(csq + binl));
                    int   bing = c * NB + binl;
                    if (dist < bd[i]) { bd[i] = dist; bi[i] = bing; }
                }
        }

        // ---- lexicographic reduce over the 4 ltx lanes ----
#pragma unroll
        for (int o = 1; o < 4; o <<= 1) {
#pragma unroll
            for (int i = 0; i < 2; ++i) {
                float od = __shfl_xor_sync(0xffffffffu, bd[i], o);
                int   oi = __shfl_xor_sync(0xffffffffu, bi[i], o);
                if (od < bd[i] || (od == bd[i] && oi < bi[i])) { bd[i] = od; bi[i] = oi; }
            }
        }
        if (ltx == 0) {
            sRd[wtx * 64 + tb]     = bd[0];  sRi[wtx * 64 + tb]     = bi[0];
            sRd[wtx * 64 + tb + 8] = bd[1];  sRi[wtx * 64 + tb + 8] = bi[1];
        }
        __syncthreads();

        if (tid < TT) {
            float d0 = sRd[tid], d1 = sRd[64 + tid];
            int   i0 = sRi[tid], i1 = sRi[64 + tid];
            int idx = (d1 < d0 || (d1 == d0 && i1 < i0)) ? i1 : i0;
            sIdx[tid] = idx;
            out_c[(size_t)(s * BDIM + b) * TDIM + t0 + tid] = (float)idx;
        }
        __syncthreads();

        // ---- residual update + commitment loss ----
        {
            int t   = tid >> 2;
            int ko  = (tid & 3) * 64;
            int idx = sIdx[t];
            const float4* cv = (const float4*)(cbs + (size_t)(s * BINS + idx) * DDIM + ko);
            float* rp = sR + t * RS + ko;
            float  lsum = 0.f;
#pragma unroll
            for (int q = 0; q < 16; ++q) {
                float4 v  = cv[q];
                float a0 = rp[q * 4 + 0] - v.x;
                float a1 = rp[q * 4 + 1] - v.y;
                float a2 = rp[q * 4 + 2] - v.z;
                float a3 = rp[q * 4 + 3] - v.w;
                rp[q * 4 + 0] = a0; rp[q * 4 + 1] = a1;
                rp[q * 4 + 2] = a2; rp[q * 4 + 3] = a3;
                lsum += a0 * a0 + a1 * a1 + a2 * a2 + a3 * a3;
            }
            lossLocal += (double)lsum;
        }
        // next chunk-loop top sync orders sR writes before GEMM reads
    }
    __syncthreads();

    // ---- epilogue: quantized = x - final residual ----
#pragma unroll
    for (int it = 0; it < 16; ++it) {
        int f  = tid + it * 256;
        int k  = f >> 4;
        int t4 = f & 15;
        const float4 v = *(const float4*)(x + (size_t)(b * DDIM + k) * TDIM + t0 + t4 * 4);
        int tl = t4 * 4;
        float4 o;
        o.x = v.x - sR[(tl + 0) * RS + k];
        o.y = v.y - sR[(tl + 1) * RS + k];
        o.z = v.z - sR[(tl + 2) * RS + k];
        o.w = v.w - sR[(tl + 3) * RS + k];
        *(float4*)(out_q + (size_t)(b * DDIM + k) * TDIM + t0 + t4 * 4) = o;
    }

    // ---- per-CTA loss partial (deterministic) ----
    int lane = tid & 31;
#pragma unroll
    for (int o = 16; o; o >>= 1) lossLocal += __shfl_down_sync(0xffffffffu, lossLocal, o);
    if (lane == 0) sWD[w] = lossLocal;
    __syncthreads();
    if (tid == 0) {
        double t = 0.0;
        for (int i = 0; i < 8; ++i) t += sWD[i];
        g_losspart[blockIdx.x] = t;
        __threadfence();
        unsigned old = atomicAdd(&g_ctr, 1u);
        *sFlg = (old == NTILE - 1) ? 1 : 0;
    }
    __syncthreads();

    // ---- last CTA finalizes scalars (fixed-order, deterministic) ----
    if (*sFlg && tid < 32) {
        __threadfence();
        double ssum = 0.0;
        for (int i = lane; i < NTILE; i += 32) ssum += __ldcg(&g_losspart[i]);
#pragma unroll
        for (int o = 16; o; o >>= 1) ssum += __shfl_down_sync(0xffffffffu, ssum, o);
        if (lane == 0) {
            int   iv = *srp;
            float fv = __int_as_float(iv);
            double sr = (iv > 0 && iv < 100000000) ? (double)iv : (double)fv;
            out[QELEMS + CELEMS]     = (float)((double)NQ * 10.0 * sr / 1000.0);
            out[QELEMS + CELEMS + 1] = (float)(ssum / (4.0 * (double)NQ * (double)QELEMS));
            atomicExch(&g_ctr, 0u);   // reset for next graph replay
        }
    }
}

// ---------------------------------------------------------------------------
extern "C" void kernel_launch(void* const* d_in, const int* in_sizes, int n_in,
                              void* d_out, int out_size) {
    const float* x   = nullptr;
    const float* cbs = nullptr;
    const int*   srp = nullptr;
    for (int i = 0; i < n_in; ++i) {
        if (in_sizes[i] == QELEMS)                x   = (const float*)d_in[i];
        else if (in_sizes[i] == NQ * BINS * DDIM) cbs = (const float*)d_in[i];
        else                                      srp = (const int*)d_in[i];
    }
    float* out = (float*)d_out;

    cudaFuncSetAttribute(rvq_main, cudaFuncAttributeMaxDynamicSharedMemorySize, SMEM_BYTES);

    cbsq_kernel<<<(NQ * BINS * 32) / 256, 256>>>(cbs);
    rvq_main<<<NTILE, 256, SMEM_BYTES>>>(x, cbs, srp, out);
}

// round 8
// speedup vs baseline: 1.1165x; 1.0446x over previous
#include <cuda_runtime.h>
#include <cstdint>
#include <cstddef>

// Problem constants
#define BDIM 8
#define DDIM 256
#define TDIM 8192
#define NQ 8
#define BINS 1024
#define TT 64                        // tokens per CTA
#define NB 64                        // bins per chunk
#define NCHUNK 16                    // chunks per stage
#define NG (NQ * NCHUNK)             // 128 total chunks
#define RS 260                       // padded row stride (floats)
#define NTILE ((BDIM * TDIM) / TT)   // 1024 CTAs
#define NT 128                       // threads per CTA
#define QELEMS (BDIM * DDIM * TDIM)  // 16777216
#define CELEMS (NQ * BDIM * TDIM)    // 524288

// SMEM layout (float offsets)
#define OFF_R 0
#define OFF_C0 (TT * RS)             // 16640
#define OFF_C1 (2 * TT * RS)         // 33280
#define OFF_IDX (3 * TT * RS)        // 64 ints
#define OFF_RD (OFF_IDX + 64)        // 256 floats (4 warps x 64 tokens)
#define OFF_RI (OFF_RD + 256)        // 256 ints
#define OFF_WD (OFF_RI + 256)        // 4 doubles
#define OFF_FLAG (OFF_WD + 8)
#define SMEM_FLOATS (OFF_FLAG + 8)
#define SMEM_BYTES (SMEM_FLOATS * 4) // ~202 KB

__device__ float    g_cbsq[NQ * BINS];
__device__ double   g_losspart[NTILE];
__device__ unsigned g_ctr;

// ---------------------------------------------------------------------------
// Precompute ||c||^2 per codebook row. One warp per bin.
// ---------------------------------------------------------------------------
__global__ void cbsq_kernel(const float* __restrict__ cbs) {
    int gid  = blockIdx.x * blockDim.x + threadIdx.x;
    int w    = gid >> 5;
    int lane = gid & 31;
    const float* row = cbs + (size_t)w * DDIM;
    float s = 0.f;
#pragma unroll
    for (int k = 0; k < DDIM; k += 32) {
        float v = row[k + lane];
        s = fmaf(v, v, s);
    }
#pragma unroll
    for (int o = 16; o; o >>= 1) s += __shfl_xor_sync(0xffffffffu, s, o);
    if (lane == 0) g_cbsq[w] = s;
}

// ---------------------------------------------------------------------------
// Async prefetch of one 64-bin codebook chunk into SMEM (row-padded to RS).
// 128 threads, 32 x 16B each.
// ---------------------------------------------------------------------------
__device__ __forceinline__ void prefetch_chunk(const float* __restrict__ cbs,
                                               int g, float* __restrict__ sCbuf,
                                               int tid) {
    int s = g >> 4, c = g & 15;
    const float* src = cbs + (size_t)(s * BINS + c * NB) * DDIM;
    unsigned dstbase = (unsigned)__cvta_generic_to_shared(sCbuf);
#pragma unroll
    for (int it = 0; it < 32; ++it) {
        int f   = tid + it * NT;    // float4 index, 0..4095
        int row = f >> 6;           // bin row 0..63
        int c4  = f & 63;           // float4 within row
        unsigned     dst = dstbase + (unsigned)((row * RS + c4 * 4) * 4);
        const float* gp  = src + row * DDIM + c4 * 4;
        asm volatile("cp.async.cg.shared.global [%0], [%1], 16;\n" ::"r"(dst), "l"(gp));
    }
    asm volatile("cp.async.commit_group;\n");
}

// non-volatile: pure computation, ptxas may schedule freely
#define FMA2(d, a, b) \
    asm("fma.rn.f32x2 %0, %1, %2, %0;" : "+l"(d) : "l"(a), "l"(b))

// ---------------------------------------------------------------------------
// Fused RVQ kernel. One CTA = 64 tokens, 128 threads.
// Thread tile: 8 tokens x 4 bins. Warp = 64 tokens x 16 bins.
//   lane: lty = l>>2 (token base, rows consecutive across lanes -> no bank
//   conflicts), ltx = l&3 (bin within consecutive 4-row group).
//   thread tokens = {lty + 8i}, i=0..7;  thread bins = w*16 + ltx + 4j, j=0..3.
// acc: single f32x2 per (tok,bin) = 64 regs; r loaded one token at a time.
// ---------------------------------------------------------------------------
__global__ __launch_bounds__(NT, 1) void rvq_main(const float* __restrict__ x,
                                                  const float* __restrict__ cbs,
                                                  const int* __restrict__ srp,
                                                  float* __restrict__ out) {
    extern __shared__ float sm[];
    float*  sR   = sm + OFF_R;
    int*    sIdx = (int*)(sm + OFF_IDX);
    float*  sRd  = sm + OFF_RD;
    int*    sRi  = (int*)(sm + OFF_RI);
    double* sWD  = (double*)(sm + OFF_WD);
    int*    sFlg = (int*)(sm + OFF_FLAG);

    const int tid = threadIdx.x;
    const int w   = tid >> 5;   // 0..3
    const int l   = tid & 31;
    const int lty = l >> 2;     // 0..7 token base
    const int ltx = l & 3;      // 0..3 bin offset
    const int b   = blockIdx.x >> 7;
    const int t0  = (blockIdx.x & 127) * TT;

    float* out_q = out;
    float* out_c = out + QELEMS;

    // ---- prologue: load + transpose x tile into sR[t][k] ----
#pragma unroll
    for (int it = 0; it < 32; ++it) {
        int f  = tid + it * NT;
        int k  = f >> 4;
        int t4 = f & 15;
        float4 v = *(const float4*)(x + (size_t)(b * DDIM + k) * TDIM + t0 + t4 * 4);
        int tl = t4 * 4;
        sR[(tl + 0) * RS + k] = v.x;
        sR[(tl + 1) * RS + k] = v.y;
        sR[(tl + 2) * RS + k] = v.z;
        sR[(tl + 3) * RS + k] = v.w;
    }
    prefetch_chunk(cbs, 0, sm + OFF_C0, tid);

    double lossLocal = 0.0;
    const float* Rb = sR + lty * RS;          // tokens lty + 8i

    for (int s = 0; s < NQ; ++s) {
        float bd[8];
        int   bi[8];
#pragma unroll
        for (int i = 0; i < 8; ++i) { bd[i] = 3.4e38f; bi[i] = 0; }

        for (int c = 0; c < NCHUNK; ++c) {
            int g = s * NCHUNK + c;
            const float* sC = sm + ((g & 1) ? OFF_C1 : OFF_C0);

            asm volatile("cp.async.wait_group 0;\n");
            __syncthreads();   // chunk g visible; everyone done with other buffer

            if (g + 1 < NG)
                prefetch_chunk(cbs, g + 1, sm + ((g & 1) ? OFF_C0 : OFF_C1), tid);

            const float* Cb = sC + (w * 16 + ltx) * RS;   // bins +4j

            unsigned long long acc[8][4];
#pragma unroll
            for (int i = 0; i < 8; ++i)
#pragma unroll
                for (int j = 0; j < 4; ++j) acc[i][j] = 0ull;

#pragma unroll 2
            for (int k4 = 0; k4 < DDIM; k4 += 4) {
                ulonglong2 cc[4];
#pragma unroll
                for (int j = 0; j < 4; ++j)
                    cc[j] = *(const ulonglong2*)(Cb + (j * 4) * RS + k4);
#pragma unroll
                for (int i = 0; i < 8; ++i) {
                    ulonglong2 r = *(const ulonglong2*)(Rb + (i * 8) * RS + k4);
#pragma unroll
                    for (int j = 0; j < 4; ++j) {
                        FMA2(acc[i][j], r.x, cc[j].x);
                        FMA2(acc[i][j], r.y, cc[j].y);
                    }
                }
            }

            // ---- distances + running argmin (chunk,j ascending = bins ascending) ----
            const float* csq = &g_cbsq[s * BINS + c * NB];
#pragma unroll
            for (int i = 0; i < 8; ++i)
#pragma unroll
                for (int j = 0; j < 4; ++j) {
                    float ax, ay;
                    asm("mov.b64 {%0,%1}, %2;" : "=f"(ax), "=f"(ay) : "l"(acc[i][j]));
                    float dot  = ax + ay;
                    int   binl = w * 16 + ltx + j * 4;
                    float dist = fmaf(-2.f, dot, __ldg(csq + binl));
                    if (dist < bd[i]) { bd[i] = dist; bi[i] = c * NB + binl; }
                }
        }

        // ---- lexicographic reduce over the 4 ltx lanes ----
#pragma unroll
        for (int o = 1; o < 4; o <<= 1) {
#pragma unroll
            for (int i = 0; i < 8; ++i) {
                float od = __shfl_xor_sync(0xffffffffu, bd[i], o);
                int   oi = __shfl_xor_sync(0xffffffffu, bi[i], o);
                if (od < bd[i] || (od == bd[i] && oi < bi[i])) { bd[i] = od; bi[i] = oi; }
            }
        }
        if (ltx == 0) {
#pragma unroll
            for (int i = 0; i < 8; ++i) {
                sRd[w * 64 + lty + 8 * i] = bd[i];
                sRi[w * 64 + lty + 8 * i] = bi[i];
            }
        }
        __syncthreads();

        // ---- reduce across the 4 warps; write codes ----
        if (tid < TT) {
            float d   = sRd[tid];
            int   idx = sRi[tid];
#pragma unroll
            for (int ww = 1; ww < 4; ++ww) {
                float dw = sRd[ww * 64 + tid];
                int   iw = sRi[ww * 64 + tid];
                if (dw < d || (dw == d && iw < idx)) { d = dw; idx = iw; }
            }
            sIdx[tid] = idx;
            out_c[(size_t)(s * BDIM + b) * TDIM + t0 + tid] = (float)idx;
        }
        __syncthreads();

        // ---- residual update + commitment loss (thread = half a token) ----
        {
            int t   = tid >> 1;
            int ko  = (tid & 1) * 128;
            int idx = sIdx[t];
            const float4* cv = (const float4*)(cbs + (size_t)(s * BINS + idx) * DDIM + ko);
            float* rp = sR + t * RS + ko;
            float  lsum = 0.f;
#pragma unroll
            for (int q = 0; q < 32; ++q) {
                float4 v  = cv[q];
                float a0 = rp[q * 4 + 0] - v.x;
                float a1 = rp[q * 4 + 1] - v.y;
                float a2 = rp[q * 4 + 2] - v.z;
                float a3 = rp[q * 4 + 3] - v.w;
                rp[q * 4 + 0] = a0; rp[q * 4 + 1] = a1;
                rp[q * 4 + 2] = a2; rp[q * 4 + 3] = a3;
                lsum += a0 * a0 + a1 * a1 + a2 * a2 + a3 * a3;
            }
            lossLocal += (double)lsum;
        }
        // next chunk-loop top sync orders sR writes before GEMM reads
    }
    __syncthreads();

    // ---- epilogue: quantized = x - final residual ----
#pragma unroll
    for (int it = 0; it < 32; ++it) {
        int f  = tid + it * NT;
        int k  = f >> 4;
        int t4 = f & 15;
        const float4 v = *(const float4*)(x + (size_t)(b * DDIM + k) * TDIM + t0 + t4 * 4);
        int tl = t4 * 4;
        float4 o;
        o.x = v.x - sR[(tl + 0) * RS + k];
        o.y = v.y - sR[(tl + 1) * RS + k];
        o.z = v.z - sR[(tl + 2) * RS + k];
        o.w = v.w - sR[(tl + 3) * RS + k];
        *(float4*)(out_q + (size_t)(b * DDIM + k) * TDIM + t0 + t4 * 4) = o;
    }

    // ---- per-CTA loss partial (deterministic) ----
#pragma unroll
    for (int o = 16; o; o >>= 1) lossLocal += __shfl_down_sync(0xffffffffu, lossLocal, o);
    if (l == 0) sWD[w] = lossLocal;
    __syncthreads();
    if (tid == 0) {
        double t = sWD[0] + sWD[1] + sWD[2] + sWD[3];
        g_losspart[blockIdx.x] = t;
        __threadfence();
        unsigned old = atomicAdd(&g_ctr, 1u);
        *sFlg = (old == NTILE - 1) ? 1 : 0;
    }
    __syncthreads();

    // ---- last CTA finalizes scalars (fixed-order, deterministic) ----
    if (*sFlg && tid < 32) {
        __threadfence();
        double ssum = 0.0;
        for (int i = l; i < NTILE; i += 32) ssum += __ldcg(&g_losspart[i]);
#pragma unroll
        for (int o = 16; o; o >>= 1) ssum += __shfl_down_sync(0xffffffffu, ssum, o);
        if (l == 0) {
            int   iv = *srp;
            float fv = __int_as_float(iv);
            double sr = (iv > 0 && iv < 100000000) ? (double)iv : (double)fv;
            out[QELEMS + CELEMS]     = (float)((double)NQ * 10.0 * sr / 1000.0);
            out[QELEMS + CELEMS + 1] = (float)(ssum / (4.0 * (double)NQ * (double)QELEMS));
            atomicExch(&g_ctr, 0u);   // reset for next graph replay
        }
    }
}

// ---------------------------------------------------------------------------
extern "C" void kernel_launch(void* const* d_in, const int* in_sizes, int n_in,
                              void* d_out, int out_size) {
    const float* x   = nullptr;
    const float* cbs = nullptr;
    const int*   srp = nullptr;
    for (int i = 0; i < n_in; ++i) {
        if (in_sizes[i] == QELEMS)                x   = (const float*)d_in[i];
        else if (in_sizes[i] == NQ * BINS * DDIM) cbs = (const float*)d_in[i];
        else                                      srp = (const int*)d_in[i];
    }
    float* out = (float*)d_out;

    cudaFuncSetAttribute(rvq_main, cudaFuncAttributeMaxDynamicSharedMemorySize, SMEM_BYTES);

    cbsq_kernel<<<(NQ * BINS * 32) / 256, 256>>>(cbs);
    rvq_main<<<NTILE, NT, SMEM_BYTES>>>(x, cbs, srp, out);
}